// round 1
// baseline (speedup 1.0000x reference)
#include <cuda_runtime.h>
#include <math.h>

#define L_  2048
#define E_  1024
#define H_  16
#define D_  64

// Scratch (device globals; allocation-free per harness rules)
__device__ float g_q[H_ * L_ * D_];     // [H, L, D]
__device__ float g_k[H_ * L_ * D_];
__device__ float g_v[H_ * L_ * D_];
__device__ float g_attn[L_ * E_];       // attention output, [L, E]
__device__ float g_ln[L_ * E_];         // layernormed attention

// ---------------------------------------------------------------------------
// SGEMM NT core: C[m,n] = sum_k A[m*lda+k] * B[n*ldb+k]
// 128x128 tile, BK=16, 256 threads, 8x8 per thread
// ---------------------------------------------------------------------------
__device__ __forceinline__ void sgemm_nt_core(
    const float* __restrict__ Ab, const float* __restrict__ Bb,
    int lda, int ldb, int K,
    float (&acc)[8][8], float (*As)[132], float (*Bs)[132])
{
    const int tx   = threadIdx.x;
    const int trow = tx >> 4;
    const int tcol = tx & 15;
    for (int k0 = 0; k0 < K; k0 += 16) {
        #pragma unroll
        for (int q = 0; q < 2; q++) {
            int id = tx + q * 256;          // 0..511
            int r  = id >> 2;               // 0..127
            int c4 = id & 3;                // 0..3
            float4 va = *(const float4*)(Ab + (size_t)r * lda + k0 + c4 * 4);
            As[c4*4+0][r] = va.x; As[c4*4+1][r] = va.y;
            As[c4*4+2][r] = va.z; As[c4*4+3][r] = va.w;
            float4 vb = *(const float4*)(Bb + (size_t)r * ldb + k0 + c4 * 4);
            Bs[c4*4+0][r] = vb.x; Bs[c4*4+1][r] = vb.y;
            Bs[c4*4+2][r] = vb.z; Bs[c4*4+3][r] = vb.w;
        }
        __syncthreads();
        #pragma unroll
        for (int kk = 0; kk < 16; kk++) {
            float ar[8], br[8];
            #pragma unroll
            for (int i = 0; i < 4; i++) {
                float2 a2 = *(const float2*)&As[kk][trow*8 + 2*i];
                ar[2*i] = a2.x; ar[2*i+1] = a2.y;
                float2 b2 = *(const float2*)&Bs[kk][tcol*8 + 2*i];
                br[2*i] = b2.x; br[2*i+1] = b2.y;
            }
            #pragma unroll
            for (int i = 0; i < 8; i++)
                #pragma unroll
                for (int j = 0; j < 8; j++)
                    acc[i][j] = fmaf(ar[i], br[j], acc[i][j]);
        }
        __syncthreads();
    }
}

// ---------------------------------------------------------------------------
// Kernel 1: QKV projections. z selects which weight; output scattered to
// head-major [H, L, D] layout.
// ---------------------------------------------------------------------------
__global__ __launch_bounds__(256) void qkv_gemm(
    const float* __restrict__ X,
    const float* __restrict__ Wq, const float* __restrict__ Bq,
    const float* __restrict__ Wk, const float* __restrict__ Bk,
    const float* __restrict__ Wv, const float* __restrict__ Bv)
{
    __shared__ float As[16][132];
    __shared__ float Bs[16][132];
    const int z = blockIdx.z;
    const float* W    = (z == 0) ? Wq : (z == 1) ? Wk : Wv;
    const float* bias = (z == 0) ? Bq : (z == 1) ? Bk : Bv;
    float* Out        = (z == 0) ? g_q : (z == 1) ? g_k : g_v;

    const float* Ab = X + (size_t)blockIdx.x * 128 * E_;
    const float* Bb = W + (size_t)blockIdx.y * 128 * E_;
    float acc[8][8];
    #pragma unroll
    for (int i = 0; i < 8; i++)
        #pragma unroll
        for (int j = 0; j < 8; j++) acc[i][j] = 0.f;

    sgemm_nt_core(Ab, Bb, E_, E_, E_, acc, As, Bs);

    const int trow = threadIdx.x >> 4, tcol = threadIdx.x & 15;
    int m0 = blockIdx.x * 128 + trow * 8;
    int n0 = blockIdx.y * 128 + tcol * 8;
    #pragma unroll
    for (int i = 0; i < 8; i++) {
        int m = m0 + i;
        #pragma unroll
        for (int j = 0; j < 8; j++) {
            int n = n0 + j;
            float val = acc[i][j] + bias[n];
            Out[(((n >> 6) * L_) + m) * D_ + (n & 63)] = val;
        }
    }
}

// ---------------------------------------------------------------------------
// Kernel 2: xPos rotary on q (upscale, + 1/sqrt(D)) and k (downscale),
// in place over [H, L, D]. One thread per (h, t, dim-pair).
// ---------------------------------------------------------------------------
__global__ __launch_bounds__(256) void xpos_kernel()
{
    int idx = blockIdx.x * blockDim.x + threadIdx.x;   // < H*L*32
    int i = idx & 31;
    int t = (idx >> 5) & (L_ - 1);
    int h = idx >> 16;

    float pos  = (float)(t - L_ / 2);
    float base = (2.0f * i + 0.4f * D_) / (1.4f * D_);
    float sc   = powf(base, pos * (1.0f / 512.0f));
    float invf = powf(10000.0f, -(float)i / 32.0f);
    float sn, cs;
    sincosf((float)t * invf, &sn, &cs);

    int off = ((h * L_) + t) * D_ + 2 * i;

    float q0 = g_q[off], q1 = g_q[off + 1];
    float cq = cs * sc, sq = sn * sc;
    g_q[off]     = (q0 * cq - q1 * sq) * 0.125f;   // * D^-0.5
    g_q[off + 1] = (q1 * cq + q0 * sq) * 0.125f;

    float isc = 1.0f / sc;
    float ck = cs * isc, sk = sn * isc;
    float k0 = g_k[off], k1 = g_k[off + 1];
    g_k[off]     = k0 * ck - k1 * sk;
    g_k[off + 1] = k1 * ck + k0 * sk;
}

// ---------------------------------------------------------------------------
// Kernel 3: S = q k^T + mask + rel_pos, written as raw logits into aw buffer
// ---------------------------------------------------------------------------
__global__ __launch_bounds__(256) void scores_gemm(
    const float* __restrict__ mask, const float* __restrict__ rel,
    float* __restrict__ aw)
{
    __shared__ float As[16][132];
    __shared__ float Bs[16][132];
    const int h = blockIdx.z;
    const float* Ab = g_q + (size_t)h * L_ * D_ + (size_t)blockIdx.x * 128 * D_;
    const float* Bb = g_k + (size_t)h * L_ * D_ + (size_t)blockIdx.y * 128 * D_;
    float acc[8][8];
    #pragma unroll
    for (int i = 0; i < 8; i++)
        #pragma unroll
        for (int j = 0; j < 8; j++) acc[i][j] = 0.f;

    sgemm_nt_core(Ab, Bb, D_, D_, D_, acc, As, Bs);

    const int trow = threadIdx.x >> 4, tcol = threadIdx.x & 15;
    int m0 = blockIdx.x * 128 + trow * 8;
    int n0 = blockIdx.y * 128 + tcol * 8;
    size_t hbase = (size_t)h * L_ * L_;
    #pragma unroll
    for (int i = 0; i < 8; i++) {
        int m = m0 + i;
        #pragma unroll
        for (int j = 0; j < 8; j++) {
            int n = n0 + j;
            size_t idx = hbase + (size_t)m * L_ + n;
            aw[idx] = acc[i][j] + mask[m * L_ + n] + rel[idx];
        }
    }
}

// ---------------------------------------------------------------------------
// Kernel 4: row softmax in place over aw (H*L rows of L)
// ---------------------------------------------------------------------------
__global__ __launch_bounds__(256) void softmax_kernel(float* __restrict__ aw)
{
    __shared__ float red[8];
    __shared__ float bval;
    size_t row = blockIdx.x;
    float* p = aw + row * L_;
    int tx = threadIdx.x, lane = tx & 31, warp = tx >> 5;

    float v[8];
    float mx = -3.4e38f;
    #pragma unroll
    for (int j = 0; j < 8; j++) { v[j] = p[tx + j * 256]; mx = fmaxf(mx, v[j]); }
    #pragma unroll
    for (int o = 16; o > 0; o >>= 1) mx = fmaxf(mx, __shfl_xor_sync(0xffffffffu, mx, o));
    if (lane == 0) red[warp] = mx;
    __syncthreads();
    if (tx == 0) {
        float m = red[0];
        #pragma unroll
        for (int w = 1; w < 8; w++) m = fmaxf(m, red[w]);
        bval = m;
    }
    __syncthreads();
    mx = bval;

    float s = 0.f;
    #pragma unroll
    for (int j = 0; j < 8; j++) { v[j] = expf(v[j] - mx); s += v[j]; }
    #pragma unroll
    for (int o = 16; o > 0; o >>= 1) s += __shfl_xor_sync(0xffffffffu, s, o);
    if (lane == 0) red[warp] = s;
    __syncthreads();
    if (tx == 0) {
        float t = 0.f;
        #pragma unroll
        for (int w = 0; w < 8; w++) t += red[w];
        bval = 1.0f / t;
    }
    __syncthreads();
    float inv = bval;
    #pragma unroll
    for (int j = 0; j < 8; j++) p[tx + j * 256] = v[j] * inv;
}

// ---------------------------------------------------------------------------
// Kernel 5: attn = aw @ v per head. NN GEMM: M=2048, N=64, K=2048.
// Block computes 64x64 (TM=TN=4), BK=32. Output scattered into [L, E].
// ---------------------------------------------------------------------------
__global__ __launch_bounds__(256) void av_gemm(const float* __restrict__ aw)
{
    __shared__ float As[32][68];
    __shared__ float Bs[32][68];
    const int h = blockIdx.z;
    const float* A = aw + (size_t)h * L_ * L_;  // [L, L]
    const float* B = g_v + (size_t)h * L_ * D_; // [L, D]
    const int tx = threadIdx.x;
    const int trow = tx >> 4, tcol = tx & 15;
    const int m0 = blockIdx.x * 64;

    float acc[4][4];
    #pragma unroll
    for (int i = 0; i < 4; i++)
        #pragma unroll
        for (int j = 0; j < 4; j++) acc[i][j] = 0.f;

    for (int k0 = 0; k0 < L_; k0 += 32) {
        #pragma unroll
        for (int q = 0; q < 2; q++) {
            int id = tx + q * 256;              // 0..511
            int r  = id >> 3, c4 = id & 7;      // A: 64 rows x 8 quads
            float4 va = *(const float4*)(A + (size_t)(m0 + r) * L_ + k0 + c4 * 4);
            As[c4*4+0][r] = va.x; As[c4*4+1][r] = va.y;
            As[c4*4+2][r] = va.z; As[c4*4+3][r] = va.w;
            int rb = id >> 4, cb4 = id & 15;    // B: 32 rows x 16 quads
            float4 vb = *(const float4*)(B + (size_t)(k0 + rb) * D_ + cb4 * 4);
            Bs[rb][cb4*4+0] = vb.x; Bs[rb][cb4*4+1] = vb.y;
            Bs[rb][cb4*4+2] = vb.z; Bs[rb][cb4*4+3] = vb.w;
        }
        __syncthreads();
        #pragma unroll
        for (int kk = 0; kk < 32; kk++) {
            float ar[4], br[4];
            #pragma unroll
            for (int i = 0; i < 2; i++) {
                float2 a2 = *(const float2*)&As[kk][trow*4 + 2*i];
                ar[2*i] = a2.x; ar[2*i+1] = a2.y;
                float2 b2 = *(const float2*)&Bs[kk][tcol*4 + 2*i];
                br[2*i] = b2.x; br[2*i+1] = b2.y;
            }
            #pragma unroll
            for (int i = 0; i < 4; i++)
                #pragma unroll
                for (int j = 0; j < 4; j++)
                    acc[i][j] = fmaf(ar[i], br[j], acc[i][j]);
        }
        __syncthreads();
    }

    #pragma unroll
    for (int i = 0; i < 4; i++) {
        int m = m0 + trow * 4 + i;
        #pragma unroll
        for (int j = 0; j < 4; j++) {
            int d = tcol * 4 + j;
            g_attn[(size_t)m * E_ + h * D_ + d] = acc[i][j];
        }
    }
}

// ---------------------------------------------------------------------------
// Kernel 6: LayerNorm over rows of g_attn -> g_ln
// ---------------------------------------------------------------------------
__global__ __launch_bounds__(256) void ln_kernel(
    const float* __restrict__ lng, const float* __restrict__ lnb)
{
    __shared__ float red[8];
    __shared__ float bval;
    int row = blockIdx.x;
    const float* x = g_attn + (size_t)row * E_;
    int tx = threadIdx.x, lane = tx & 31, warp = tx >> 5;

    float v[4];
    float s = 0.f;
    #pragma unroll
    for (int j = 0; j < 4; j++) { v[j] = x[tx + j * 256]; s += v[j]; }
    #pragma unroll
    for (int o = 16; o > 0; o >>= 1) s += __shfl_xor_sync(0xffffffffu, s, o);
    if (lane == 0) red[warp] = s;
    __syncthreads();
    if (tx == 0) {
        float t = 0.f;
        #pragma unroll
        for (int w = 0; w < 8; w++) t += red[w];
        bval = t * (1.0f / E_);
    }
    __syncthreads();
    float mu = bval;

    float s2 = 0.f;
    #pragma unroll
    for (int j = 0; j < 4; j++) { float d = v[j] - mu; s2 += d * d; }
    #pragma unroll
    for (int o = 16; o > 0; o >>= 1) s2 += __shfl_xor_sync(0xffffffffu, s2, o);
    if (lane == 0) red[warp] = s2;
    __syncthreads();
    if (tx == 0) {
        float t = 0.f;
        #pragma unroll
        for (int w = 0; w < 8; w++) t += red[w];
        bval = rsqrtf(t * (1.0f / E_) + 1e-5f);
    }
    __syncthreads();
    float rs = bval;

    #pragma unroll
    for (int j = 0; j < 4; j++) {
        int c = tx + j * 256;
        g_ln[(size_t)row * E_ + c] = (v[j] - mu) * rs * lng[c] + lnb[c];
    }
}

// ---------------------------------------------------------------------------
// Kernel 7: out = ln @ wo^T + bo
// ---------------------------------------------------------------------------
__global__ __launch_bounds__(256) void out_gemm(
    const float* __restrict__ Wo, const float* __restrict__ Bo,
    float* __restrict__ out)
{
    __shared__ float As[16][132];
    __shared__ float Bs[16][132];
    const float* Ab = g_ln + (size_t)blockIdx.x * 128 * E_;
    const float* Bb = Wo   + (size_t)blockIdx.y * 128 * E_;
    float acc[8][8];
    #pragma unroll
    for (int i = 0; i < 8; i++)
        #pragma unroll
        for (int j = 0; j < 8; j++) acc[i][j] = 0.f;

    sgemm_nt_core(Ab, Bb, E_, E_, E_, acc, As, Bs);

    const int trow = threadIdx.x >> 4, tcol = threadIdx.x & 15;
    int m0 = blockIdx.x * 128 + trow * 8;
    int n0 = blockIdx.y * 128 + tcol * 8;
    #pragma unroll
    for (int i = 0; i < 8; i++) {
        int m = m0 + i;
        #pragma unroll
        for (int j = 0; j < 8; j++) {
            int n = n0 + j;
            out[(size_t)m * E_ + n] = acc[i][j] + Bo[n];
        }
    }
}

// ---------------------------------------------------------------------------
extern "C" void kernel_launch(void* const* d_in, const int* in_sizes, int n_in,
                              void* d_out, int out_size)
{
    const float* query = (const float*)d_in[0];
    const float* rel   = (const float*)d_in[1];
    const float* mask  = (const float*)d_in[2];
    const float* wq    = (const float*)d_in[3];
    const float* bq    = (const float*)d_in[4];
    const float* wk    = (const float*)d_in[5];
    const float* bk    = (const float*)d_in[6];
    const float* wv    = (const float*)d_in[7];
    const float* bv    = (const float*)d_in[8];
    const float* wo    = (const float*)d_in[9];
    const float* bo    = (const float*)d_in[10];
    const float* lng   = (const float*)d_in[11];
    const float* lnb   = (const float*)d_in[12];

    float* out = (float*)d_out;                 // [L, E]
    float* aw  = out + (size_t)L_ * E_;         // [H, L, L]

    qkv_gemm<<<dim3(16, 8, 3), 256>>>(query, wq, bq, wk, bk, wv, bv);
    xpos_kernel<<<4096, 256>>>();
    scores_gemm<<<dim3(16, 16, 16), 256>>>(mask, rel, aw);
    softmax_kernel<<<H_ * L_, 256>>>(aw);
    av_gemm<<<dim3(32, 1, 16), 256>>>(aw);
    ln_kernel<<<L_, 256>>>(lng, lnb);
    out_gemm<<<dim3(16, 8, 1), 256>>>(wo, bo, out);
}

// round 4
// speedup vs baseline: 2.8809x; 2.8809x over previous
#include <cuda_runtime.h>
#include <cstdint>
#include <math.h>

#define L_  2048
#define E_  1024
#define H_  16
#define D_  64

// ---------------- scratch (device globals; no allocations allowed) ----------
__device__ float g_q[H_ * L_ * D_];      // [H, L, D]
__device__ float g_k[H_ * L_ * D_];      // [H, L, D]
__device__ float g_v[H_ * L_ * D_];      // [H, L, D]
__device__ float g_attn[L_ * E_];        // attention output, [L, E]
__device__ float g_ln[L_ * E_];          // layernormed attention

extern __shared__ char dynsmem[];

// ---------------- helpers ---------------------------------------------------
__device__ __forceinline__ uint32_t smem_u32(const void* p) {
    uint32_t a;
    asm("{ .reg .u64 t; cvta.to.shared.u64 t, %1; cvt.u32.u64 %0, t; }"
        : "=r"(a) : "l"(p));
    return a;
}
__device__ __forceinline__ void cp16(uint32_t dst, const void* src) {
    asm volatile("cp.async.cg.shared.global [%0], [%1], 16;"
                 :: "r"(dst), "l"(src) : "memory");
}
__device__ __forceinline__ uint32_t f2tf(float f) {
    uint32_t u;
    asm("cvt.rna.tf32.f32 %0, %1;" : "=r"(u) : "f"(f));
    return u;
}
#define CP_COMMIT()  asm volatile("cp.async.commit_group;" ::: "memory")
#define CP_WAIT0()   asm volatile("cp.async.wait_group 0;" ::: "memory")
#define CP_WAIT1()   asm volatile("cp.async.wait_group 1;" ::: "memory")
#define MMA4(d, a, b) asm volatile( \
    "mma.sync.aligned.m16n8k8.row.col.f32.tf32.tf32.f32 " \
    "{%0,%1,%2,%3},{%4,%5,%6,%7},{%8,%9},{%0,%1,%2,%3};" \
    : "+f"((d)[0]), "+f"((d)[1]), "+f"((d)[2]), "+f"((d)[3]) \
    : "r"((a)[0]), "r"((a)[1]), "r"((a)[2]), "r"((a)[3]), "r"((b)[0]), "r"((b)[1]))

// A tile in SMEM: 128 rows x 32 k, stride 36 floats (conflict-free frags)
// NT B tile: BN rows x 32 k, stride 36.  NN B tile (av): 32 k x 64 n, stride 68.
#define ASZ_  18432          // 128*36*4

// ---------------------------------------------------------------------------
// NT tile loader + mma stage (A row-major MxK, B row-major NxK)
// ---------------------------------------------------------------------------
template <int BN>
__device__ __forceinline__ void nt_load(uint32_t sbase, int stage,
                                        const float* __restrict__ A, int lda,
                                        const float* __restrict__ B, int ldb, int kt)
{
    constexpr int BSZ = BN * 144;
    constexpr int STG = ASZ_ + BSZ;
    const int tx = threadIdx.x;
    uint32_t ab = sbase + stage * STG;
    const float* Ak = A + kt * 32;
    #pragma unroll
    for (int i = 0; i < 4; i++) {
        int id = tx + i * 256;
        int r = id >> 3, c = id & 7;
        cp16(ab + r * 144 + c * 16, Ak + (size_t)r * lda + c * 4);
    }
    uint32_t bb = ab + ASZ_;
    const float* Bk = B + kt * 32;
    #pragma unroll
    for (int i = 0; i < BN / 32; i++) {          // FIX: was BN/64 (half tile)
        int id = tx + i * 256;
        int r = id >> 3, c = id & 7;
        cp16(bb + r * 144 + c * 16, Bk + (size_t)r * ldb + c * 4);
    }
}

template <int BN>
__device__ __forceinline__ void nt_mma(int stage, float (&acc)[4][BN / 32][4])
{
    constexpr int NT = BN / 32;
    constexpr int STG = ASZ_ + BN * 144;
    const float* As = (const float*)(dynsmem + stage * STG);
    const float* Bs = (const float*)(dynsmem + stage * STG + ASZ_);
    const int lane = threadIdx.x & 31, w = threadIdx.x >> 5;
    const int wm = (w >> 2) * 64, wn = (w & 3) * (NT * 8);
    const int lr = lane >> 2, lc = lane & 3;
    #pragma unroll
    for (int kk = 0; kk < 4; kk++) {
        uint32_t a[4][4];
        #pragma unroll
        for (int mt = 0; mt < 4; mt++) {
            const float* ap = As + (wm + mt * 16 + lr) * 36 + kk * 8 + lc;
            a[mt][0] = f2tf(ap[0]);
            a[mt][1] = f2tf(ap[8 * 36]);
            a[mt][2] = f2tf(ap[4]);
            a[mt][3] = f2tf(ap[8 * 36 + 4]);
        }
        uint32_t b[NT][2];
        #pragma unroll
        for (int nt = 0; nt < NT; nt++) {
            const float* bp = Bs + (wn + nt * 8 + lr) * 36 + kk * 8 + lc;
            b[nt][0] = f2tf(bp[0]);
            b[nt][1] = f2tf(bp[4]);
        }
        #pragma unroll
        for (int mt = 0; mt < 4; mt++)
            #pragma unroll
            for (int nt = 0; nt < NT; nt++)
                MMA4(acc[mt][nt], a[mt], b[nt]);
    }
}

template <int BN>
__device__ __forceinline__ void gemm_nt(const float* __restrict__ A, int lda,
                                        const float* __restrict__ B, int ldb,
                                        int nkt, float (&acc)[4][BN / 32][4])
{
    uint32_t sbase = smem_u32(dynsmem);
    #pragma unroll
    for (int mt = 0; mt < 4; mt++)
        #pragma unroll
        for (int nt = 0; nt < BN / 32; nt++)
            #pragma unroll
            for (int j = 0; j < 4; j++) acc[mt][nt][j] = 0.f;

    nt_load<BN>(sbase, 0, A, lda, B, ldb, 0);
    CP_COMMIT();
    for (int kt = 0; kt < nkt; kt++) {
        if (kt + 1 < nkt) {
            nt_load<BN>(sbase, (kt + 1) & 1, A, lda, B, ldb, kt + 1);
            CP_COMMIT();
            CP_WAIT1();
        } else {
            CP_WAIT0();
        }
        __syncthreads();
        nt_mma<BN>(kt & 1, acc);
        __syncthreads();
    }
}

// ---------------------------------------------------------------------------
// Kernel 1: QKV projections (z = 0/1/2), tf32 mma
// ---------------------------------------------------------------------------
__global__ __launch_bounds__(256) void qkv_tc(
    const float* __restrict__ X,
    const float* __restrict__ Wq, const float* __restrict__ Bq,
    const float* __restrict__ Wk, const float* __restrict__ Bk,
    const float* __restrict__ Wv, const float* __restrict__ Bv)
{
    const int z = blockIdx.z;
    const float* Wt   = (z == 0) ? Wq : (z == 1) ? Wk : Wv;
    const float* bias = (z == 0) ? Bq : (z == 1) ? Bk : Bv;
    float* O          = (z == 0) ? g_q : (z == 1) ? g_k : g_v;
    const float* A = X  + (size_t)blockIdx.x * 128 * E_;
    const float* B = Wt + (size_t)blockIdx.y * 128 * E_;

    float acc[4][4][4];
    gemm_nt<128>(A, E_, B, E_, E_ / 32, acc);

    const int lane = threadIdx.x & 31, w = threadIdx.x >> 5;
    const int wm = (w >> 2) * 64, wn = (w & 3) * 32;
    const int lr = lane >> 2, lc = lane & 3;
    const int m0 = blockIdx.x * 128, n0 = blockIdx.y * 128;
    #pragma unroll
    for (int mt = 0; mt < 4; mt++) {
        #pragma unroll
        for (int nt = 0; nt < 4; nt++) {
            int col = n0 + wn + nt * 8 + lc * 2;
            int h = col >> 6, d = col & 63;
            float b0 = __ldg(&bias[col]), b1 = __ldg(&bias[col + 1]);
            #pragma unroll
            for (int p = 0; p < 2; p++) {
                int row = m0 + wm + mt * 16 + lr + p * 8;
                float2 v2 = make_float2(acc[mt][nt][2 * p] + b0,
                                        acc[mt][nt][2 * p + 1] + b1);
                *(float2*)&O[((size_t)h * L_ + row) * D_ + d] = v2;
            }
        }
    }
}

// ---------------------------------------------------------------------------
// Kernel 2: xPos rotary on q (upscale + 1/sqrt(D)) and k (downscale), in place
// ---------------------------------------------------------------------------
__global__ __launch_bounds__(256) void xpos_kernel()
{
    int idx = blockIdx.x * blockDim.x + threadIdx.x;   // < H*L*32
    int i = idx & 31;
    int t = (idx >> 5) & (L_ - 1);
    int h = idx >> 16;

    float pos  = (float)(t - L_ / 2);
    float base = (2.0f * i + 0.4f * D_) / (1.4f * D_);
    float sc   = powf(base, pos * (1.0f / 512.0f));
    float invf = powf(10000.0f, -(float)i / 32.0f);
    float sn, cs;
    sincosf((float)t * invf, &sn, &cs);

    int off = ((h * L_) + t) * D_ + 2 * i;

    float q0 = g_q[off], q1 = g_q[off + 1];
    float cq = cs * sc, sq = sn * sc;
    g_q[off]     = (q0 * cq - q1 * sq) * 0.125f;
    g_q[off + 1] = (q1 * cq + q0 * sq) * 0.125f;

    float isc = 1.0f / sc;
    float ck = cs * isc, sk = sn * isc;
    float k0 = g_k[off], k1 = g_k[off + 1];
    g_k[off]     = k0 * ck - k1 * sk;
    g_k[off + 1] = k1 * ck + k0 * sk;
}

// ---------------------------------------------------------------------------
// Kernel 3: S = q k^T + mask + rel -> aw raw logits (lower-tri blocks only)
// ---------------------------------------------------------------------------
__global__ __launch_bounds__(256) void scores_tc(
    const float* __restrict__ mask, const float* __restrict__ rel,
    float* __restrict__ aw)
{
    if (blockIdx.y > blockIdx.x) return;    // strictly upper: exp -> 0, skipped
    const int h = blockIdx.z;
    const float* A = g_q + (size_t)h * L_ * D_ + (size_t)blockIdx.x * 128 * D_;
    const float* B = g_k + (size_t)h * L_ * D_ + (size_t)blockIdx.y * 128 * D_;

    float acc[4][4][4];
    gemm_nt<128>(A, D_, B, D_, D_ / 32, acc);

    const int lane = threadIdx.x & 31, w = threadIdx.x >> 5;
    const int wm = (w >> 2) * 64, wn = (w & 3) * 32;
    const int lr = lane >> 2, lc = lane & 3;
    const int m0 = blockIdx.x * 128, n0 = blockIdx.y * 128;
    size_t hbase = (size_t)h * L_ * L_;
    #pragma unroll
    for (int mt = 0; mt < 4; mt++) {
        #pragma unroll
        for (int nt = 0; nt < 4; nt++) {
            int col = n0 + wn + nt * 8 + lc * 2;
            #pragma unroll
            for (int p = 0; p < 2; p++) {
                int row = m0 + wm + mt * 16 + lr + p * 8;
                size_t idx = hbase + (size_t)row * L_ + col;
                float2 mk = *(const float2*)&mask[(size_t)row * L_ + col];
                float2 rl = *(const float2*)&rel[idx];
                float2 v2 = make_float2(acc[mt][nt][2 * p] + mk.x + rl.x,
                                        acc[mt][nt][2 * p + 1] + mk.y + rl.y);
                *(float2*)&aw[idx] = v2;
            }
        }
    }
}

// ---------------------------------------------------------------------------
// Kernel 4: causal row softmax: read first t+1 logits, zero-fill the rest
// ---------------------------------------------------------------------------
__global__ __launch_bounds__(256) void softmax_kernel(float* __restrict__ aw)
{
    __shared__ float red[8];
    __shared__ float bval;
    size_t row = blockIdx.x;
    int t = (int)(row & (L_ - 1));
    int len = t + 1;
    float* p = aw + row * L_;
    int tx = threadIdx.x, lane = tx & 31, warp = tx >> 5;

    float v[8];
    float mx = -3.4e38f;
    #pragma unroll
    for (int j = 0; j < 8; j++) {
        int idx = tx + j * 256;
        v[j] = (idx < len) ? p[idx] : -3.4e38f;
        mx = fmaxf(mx, v[j]);
    }
    #pragma unroll
    for (int o = 16; o > 0; o >>= 1) mx = fmaxf(mx, __shfl_xor_sync(0xffffffffu, mx, o));
    if (lane == 0) red[warp] = mx;
    __syncthreads();
    if (tx == 0) {
        float m = red[0];
        #pragma unroll
        for (int w = 1; w < 8; w++) m = fmaxf(m, red[w]);
        bval = m;
    }
    __syncthreads();
    mx = bval;

    float s = 0.f;
    #pragma unroll
    for (int j = 0; j < 8; j++) {
        int idx = tx + j * 256;
        v[j] = (idx < len) ? expf(v[j] - mx) : 0.f;
        s += v[j];
    }
    #pragma unroll
    for (int o = 16; o > 0; o >>= 1) s += __shfl_xor_sync(0xffffffffu, s, o);
    if (lane == 0) red[warp] = s;
    __syncthreads();
    if (tx == 0) {
        float tsum = 0.f;
        #pragma unroll
        for (int w = 0; w < 8; w++) tsum += red[w];
        bval = 1.0f / tsum;
    }
    __syncthreads();
    float inv = bval;
    #pragma unroll
    for (int j = 0; j < 8; j++) p[tx + j * 256] = v[j] * inv;
}

// ---------------------------------------------------------------------------
// Kernel 5: attn = aw @ v per head (NN gemm, BN=64, causal K bound)
// ---------------------------------------------------------------------------
__device__ __forceinline__ void nn_load64(uint32_t sbase, int stage,
                                          const float* __restrict__ A, int lda,
                                          const float* __restrict__ B, int kt)
{
    constexpr int STG = ASZ_ + 8704;
    const int tx = threadIdx.x;
    uint32_t ab = sbase + stage * STG;
    const float* Ak = A + kt * 32;
    #pragma unroll
    for (int i = 0; i < 4; i++) {
        int id = tx + i * 256;
        int r = id >> 3, c = id & 7;
        cp16(ab + r * 144 + c * 16, Ak + (size_t)r * lda + c * 4);
    }
    uint32_t bb = ab + ASZ_;
    const float* Bk = B + (size_t)kt * 32 * D_;
    #pragma unroll
    for (int i = 0; i < 2; i++) {
        int id = tx + i * 256;
        int r = id >> 4, c = id & 15;           // [32 k rows][64 cols]
        cp16(bb + r * 272 + c * 16, Bk + (size_t)r * D_ + c * 4);
    }
}

__device__ __forceinline__ void nn_mma64(int stage, float (&acc)[4][2][4])
{
    constexpr int STG = ASZ_ + 8704;
    const float* As = (const float*)(dynsmem + stage * STG);
    const float* Bs = (const float*)(dynsmem + stage * STG + ASZ_);
    const int lane = threadIdx.x & 31, w = threadIdx.x >> 5;
    const int wm = (w >> 2) * 64, wn = (w & 3) * 16;
    const int lr = lane >> 2, lc = lane & 3;
    #pragma unroll
    for (int kk = 0; kk < 4; kk++) {
        uint32_t a[4][4];
        #pragma unroll
        for (int mt = 0; mt < 4; mt++) {
            const float* ap = As + (wm + mt * 16 + lr) * 36 + kk * 8 + lc;
            a[mt][0] = f2tf(ap[0]);
            a[mt][1] = f2tf(ap[8 * 36]);
            a[mt][2] = f2tf(ap[4]);
            a[mt][3] = f2tf(ap[8 * 36 + 4]);
        }
        uint32_t b[2][2];
        #pragma unroll
        for (int nt = 0; nt < 2; nt++) {
            const float* bp = Bs + (kk * 8 + lc) * 68 + wn + nt * 8 + lr;
            b[nt][0] = f2tf(bp[0]);
            b[nt][1] = f2tf(bp[4 * 68]);
        }
        #pragma unroll
        for (int mt = 0; mt < 4; mt++)
            #pragma unroll
            for (int nt = 0; nt < 2; nt++)
                MMA4(acc[mt][nt], a[mt], b[nt]);
    }
}

__global__ __launch_bounds__(256) void av_tc(const float* __restrict__ aw)
{
    const int h = blockIdx.z;
    const float* A = aw  + (size_t)h * L_ * L_ + (size_t)blockIdx.x * 128 * L_;
    const float* B = g_v + (size_t)h * L_ * D_;
    const int nkt = (blockIdx.x + 1) * 4;      // causal: K <= (bx+1)*128

    float acc[4][2][4];
    #pragma unroll
    for (int mt = 0; mt < 4; mt++)
        #pragma unroll
        for (int nt = 0; nt < 2; nt++)
            #pragma unroll
            for (int j = 0; j < 4; j++) acc[mt][nt][j] = 0.f;

    uint32_t sbase = smem_u32(dynsmem);
    nn_load64(sbase, 0, A, L_, B, 0);
    CP_COMMIT();
    for (int kt = 0; kt < nkt; kt++) {
        if (kt + 1 < nkt) {
            nn_load64(sbase, (kt + 1) & 1, A, L_, B, kt + 1);
            CP_COMMIT();
            CP_WAIT1();
        } else {
            CP_WAIT0();
        }
        __syncthreads();
        nn_mma64(kt & 1, acc);
        __syncthreads();
    }

    const int lane = threadIdx.x & 31, w = threadIdx.x >> 5;
    const int wm = (w >> 2) * 64, wn = (w & 3) * 16;
    const int lr = lane >> 2, lc = lane & 3;
    const int m0 = blockIdx.x * 128;
    #pragma unroll
    for (int mt = 0; mt < 4; mt++) {
        #pragma unroll
        for (int nt = 0; nt < 2; nt++) {
            int col = wn + nt * 8 + lc * 2;
            #pragma unroll
            for (int p = 0; p < 2; p++) {
                int row = m0 + wm + mt * 16 + lr + p * 8;
                float2 v2 = make_float2(acc[mt][nt][2 * p], acc[mt][nt][2 * p + 1]);
                *(float2*)&g_attn[(size_t)row * E_ + h * D_ + col] = v2;
            }
        }
    }
}

// ---------------------------------------------------------------------------
// Kernel 6: LayerNorm over rows of g_attn -> g_ln
// ---------------------------------------------------------------------------
__global__ __launch_bounds__(256) void ln_kernel(
    const float* __restrict__ lng, const float* __restrict__ lnb)
{
    __shared__ float red[8];
    __shared__ float bval;
    int row = blockIdx.x;
    const float* x = g_attn + (size_t)row * E_;
    int tx = threadIdx.x, lane = tx & 31, warp = tx >> 5;

    float v[4];
    float s = 0.f;
    #pragma unroll
    for (int j = 0; j < 4; j++) { v[j] = x[tx + j * 256]; s += v[j]; }
    #pragma unroll
    for (int o = 16; o > 0; o >>= 1) s += __shfl_xor_sync(0xffffffffu, s, o);
    if (lane == 0) red[warp] = s;
    __syncthreads();
    if (tx == 0) {
        float t = 0.f;
        #pragma unroll
        for (int w = 0; w < 8; w++) t += red[w];
        bval = t * (1.0f / E_);
    }
    __syncthreads();
    float mu = bval;

    float s2 = 0.f;
    #pragma unroll
    for (int j = 0; j < 4; j++) { float d = v[j] - mu; s2 += d * d; }
    #pragma unroll
    for (int o = 16; o > 0; o >>= 1) s2 += __shfl_xor_sync(0xffffffffu, s2, o);
    if (lane == 0) red[warp] = s2;
    __syncthreads();
    if (tx == 0) {
        float t = 0.f;
        #pragma unroll
        for (int w = 0; w < 8; w++) t += red[w];
        bval = rsqrtf(t * (1.0f / E_) + 1e-5f);
    }
    __syncthreads();
    float rs = bval;

    #pragma unroll
    for (int j = 0; j < 4; j++) {
        int c = tx + j * 256;
        g_ln[(size_t)row * E_ + c] = (v[j] - mu) * rs * lng[c] + lnb[c];
    }
}

// ---------------------------------------------------------------------------
// Kernel 7: out = ln @ wo^T + bo, tf32 mma
// ---------------------------------------------------------------------------
__global__ __launch_bounds__(256) void out_tc(
    const float* __restrict__ Wo, const float* __restrict__ Bo,
    float* __restrict__ out)
{
    const float* A = g_ln + (size_t)blockIdx.x * 128 * E_;
    const float* B = Wo   + (size_t)blockIdx.y * 128 * E_;

    float acc[4][4][4];
    gemm_nt<128>(A, E_, B, E_, E_ / 32, acc);

    const int lane = threadIdx.x & 31, w = threadIdx.x >> 5;
    const int wm = (w >> 2) * 64, wn = (w & 3) * 32;
    const int lr = lane >> 2, lc = lane & 3;
    const int m0 = blockIdx.x * 128, n0 = blockIdx.y * 128;
    #pragma unroll
    for (int mt = 0; mt < 4; mt++) {
        #pragma unroll
        for (int nt = 0; nt < 4; nt++) {
            int col = n0 + wn + nt * 8 + lc * 2;
            float b0 = __ldg(&Bo[col]), b1 = __ldg(&Bo[col + 1]);
            #pragma unroll
            for (int p = 0; p < 2; p++) {
                int row = m0 + wm + mt * 16 + lr + p * 8;
                float2 v2 = make_float2(acc[mt][nt][2 * p] + b0,
                                        acc[mt][nt][2 * p + 1] + b1);
                *(float2*)&out[(size_t)row * E_ + col] = v2;
            }
        }
    }
}

// ---------------------------------------------------------------------------
extern "C" void kernel_launch(void* const* d_in, const int* in_sizes, int n_in,
                              void* d_out, int out_size)
{
    const float* query = (const float*)d_in[0];
    const float* rel   = (const float*)d_in[1];
    const float* mask  = (const float*)d_in[2];
    const float* wq    = (const float*)d_in[3];
    const float* bq    = (const float*)d_in[4];
    const float* wk    = (const float*)d_in[5];
    const float* bk    = (const float*)d_in[6];
    const float* wv    = (const float*)d_in[7];
    const float* bv    = (const float*)d_in[8];
    const float* wo    = (const float*)d_in[9];
    const float* bo    = (const float*)d_in[10];
    const float* lng   = (const float*)d_in[11];
    const float* lnb   = (const float*)d_in[12];

    float* out = (float*)d_out;                 // [L, E]
    float* aw  = out + (size_t)L_ * E_;         // [H, L, L]

    const int SM_NT128 = 2 * (ASZ_ + 128 * 144);   // 73728
    const int SM_AV    = 2 * (ASZ_ + 8704);        // 54272
    cudaFuncSetAttribute(qkv_tc,    cudaFuncAttributeMaxDynamicSharedMemorySize, SM_NT128);
    cudaFuncSetAttribute(scores_tc, cudaFuncAttributeMaxDynamicSharedMemorySize, SM_NT128);
    cudaFuncSetAttribute(av_tc,     cudaFuncAttributeMaxDynamicSharedMemorySize, SM_AV);
    cudaFuncSetAttribute(out_tc,    cudaFuncAttributeMaxDynamicSharedMemorySize, SM_NT128);

    qkv_tc<<<dim3(16, 8, 3), 256, SM_NT128>>>(query, wq, bq, wk, bk, wv, bv);
    xpos_kernel<<<4096, 256>>>();
    scores_tc<<<dim3(16, 16, 16), 256, SM_NT128>>>(mask, rel, aw);
    softmax_kernel<<<H_ * L_, 256>>>(aw);
    av_tc<<<dim3(16, 1, 16), 256, SM_AV>>>(aw);
    ln_kernel<<<L_, 256>>>(lng, lnb);
    out_tc<<<dim3(16, 8, 1), 256, SM_NT128>>>(wo, bo, out);
}